// round 17
// baseline (speedup 1.0000x reference)
#include <cuda_runtime.h>

#define NATOMS 100000
#define NPAIRS 2000000
#define FDIM 64
#define RDIM 16
#define LN2F 0.6931471805599453f

typedef unsigned long long u64;

// Scratch (device globals: allocation-free per harness rules)
__device__ float g_yj[NATOMS * FDIM];   // softplus(x@Wj+bj) per atom
__device__ float g_acc[NATOMS * FDIM];  // x_i' accumulator; pairs red into it

__device__ __forceinline__ float sp(float x) {
    return fmaxf(x, 0.f) + log1pf(__expf(-fabsf(x)));
}

// ---- packed f32x2 helpers ----
__device__ __forceinline__ u64 fma2(u64 a, u64 b, u64 c) {
    u64 d;
    asm("fma.rn.f32x2 %0, %1, %2, %3;" : "=l"(d) : "l"(a), "l"(b), "l"(c));
    return d;
}
__device__ __forceinline__ u64 add2(u64 a, u64 b) {
    u64 d;
    asm("add.rn.f32x2 %0, %1, %2;" : "=l"(d) : "l"(a), "l"(b));
    return d;
}
__device__ __forceinline__ u64 mul2(u64 a, u64 b) {
    u64 d;
    asm("mul.rn.f32x2 %0, %1, %2;" : "=l"(d) : "l"(a), "l"(b));
    return d;
}
__device__ __forceinline__ u64 splat2(float v) {
    u64 r;
    asm("mov.b64 %0, {%1, %1};" : "=l"(r) : "f"(v));
    return r;
}
__device__ __forceinline__ u64 pack2(float lo, float hi) {
    u64 r;
    asm("mov.b64 %0, {%1, %2};" : "=l"(r) : "f"(lo), "f"(hi));
    return r;
}
__device__ __forceinline__ float2 unpack2(u64 v) {
    float lo, hi;
    asm("mov.b64 {%0, %1}, %2;" : "=f"(lo), "=f"(hi) : "l"(v));
    return make_float2(lo, hi);
}

// ---------------------------------------------------------------------------
// Kernel 1: node transforms. x = sp(emb)-ln2; g_acc = sp(x@Wi+bi);
// g_yj = sp(x@Wj+bj). One GEMM with N=128 (Wi|Wj concatenated).
// ---------------------------------------------------------------------------
#define NODE_TILE 64
#define XPAD 68

__global__ void __launch_bounds__(512, 2) node_kernel(
    const float* __restrict__ emb,
    const float* __restrict__ Wi, const float* __restrict__ bi,
    const float* __restrict__ Wj, const float* __restrict__ bj)
{
    __shared__ float Wc[FDIM * 128];
    __shared__ float bc[128];
    __shared__ float xs[NODE_TILE * XPAD];

    const int tid = threadIdx.x;
    for (int i = tid; i < FDIM * FDIM; i += 512) {
        const int k = i >> 6, c = i & 63;
        Wc[k * 128 + c]      = Wi[i];
        Wc[k * 128 + 64 + c] = Wj[i];
    }
    if (tid < 64) { bc[tid] = bi[tid]; bc[64 + tid] = bj[tid]; }
    __syncthreads();

    const int qp = tid & 31;
    const int ag = tid >> 5;
    const u64 bias0 = pack2(bc[qp * 4 + 0], bc[qp * 4 + 1]);
    const u64 bias1 = pack2(bc[qp * 4 + 2], bc[qp * 4 + 3]);

    const int ntiles = (NATOMS + NODE_TILE - 1) / NODE_TILE;
    for (int t = blockIdx.x; t < ntiles; t += gridDim.x) {
        for (int i = tid; i < NODE_TILE * 16; i += 512) {
            const int a = i >> 4, qq = i & 15;
            const int atom = t * NODE_TILE + a;
            if (atom < NATOMS) {
                const float4 e = *reinterpret_cast<const float4*>(
                    emb + (size_t)atom * FDIM + qq * 4);
                float4 x;
                x.x = sp(e.x) - LN2F; x.y = sp(e.y) - LN2F;
                x.z = sp(e.z) - LN2F; x.w = sp(e.w) - LN2F;
                *reinterpret_cast<float4*>(xs + a * XPAD + qq * 4) = x;
            }
        }
        __syncthreads();

        u64 acc[4][2];
        #pragma unroll
        for (int i = 0; i < 4; i++) { acc[i][0] = bias0; acc[i][1] = bias1; }

        #pragma unroll 4
        for (int k0 = 0; k0 < FDIM; k0 += 4) {
            ulonglong2 w[4];
            #pragma unroll
            for (int j = 0; j < 4; j++)
                w[j] = *reinterpret_cast<const ulonglong2*>(
                    Wc + (k0 + j) * 128 + qp * 4);
            #pragma unroll
            for (int i = 0; i < 4; i++) {
                const float4 v = *reinterpret_cast<const float4*>(
                    xs + (ag * 4 + i) * XPAD + k0);
                acc[i][0] = fma2(splat2(v.x), w[0].x, acc[i][0]);
                acc[i][1] = fma2(splat2(v.x), w[0].y, acc[i][1]);
                acc[i][0] = fma2(splat2(v.y), w[1].x, acc[i][0]);
                acc[i][1] = fma2(splat2(v.y), w[1].y, acc[i][1]);
                acc[i][0] = fma2(splat2(v.z), w[2].x, acc[i][0]);
                acc[i][1] = fma2(splat2(v.z), w[2].y, acc[i][1]);
                acc[i][0] = fma2(splat2(v.w), w[3].x, acc[i][0]);
                acc[i][1] = fma2(splat2(v.w), w[3].y, acc[i][1]);
            }
        }

        float* const dstbase = (qp < 16) ? g_acc : g_yj;
        const int col = (qp & 15) * 4;
        #pragma unroll
        for (int i = 0; i < 4; i++) {
            const int atom = t * NODE_TILE + ag * 4 + i;
            if (atom < NATOMS) {
                const float2 p0 = unpack2(acc[i][0]);
                const float2 p1 = unpack2(acc[i][1]);
                const float4 o = make_float4(sp(p0.x), sp(p0.y), sp(p1.x), sp(p1.y));
                *reinterpret_cast<float4*>(dstbase + (size_t)atom * FDIM + col) = o;
            }
        }
        __syncthreads();
    }
}

// ---------------------------------------------------------------------------
// Kernel 2: half-warp-per-pair, G entirely in registers (4 features per lane,
// 32 u64 coefficients). Zero SMEM. One red.global.add.v4.f32 per lane per
// pair -> 16 scatter messages/pair (half of the R16 v2 shape, which was
// LSU/REDG issue-bound at ~1.29 cyc/lane).
//   lane = 16*half + q ; half selects the pair, q = 4-feature group.
// ---------------------------------------------------------------------------
__global__ void __launch_bounds__(256) pair_kernel(
    const int* __restrict__ pidx,
    const float* __restrict__ fij,
    const float* __restrict__ G)
{
    const int lane = threadIdx.x & 31;
    const int q    = lane & 15;   // feature group: features 4q..4q+3
    const int half = lane >> 4;   // which of the 2 pairs this half-warp owns

    // Ga[r] = {G[4q+0][r], G[4q+1][r]},  Gb[r] = {G[4q+2][r], G[4q+3][r]}
    u64 Ga[RDIM], Gb[RDIM];
    {
        const float4* g0 = reinterpret_cast<const float4*>(G + (4 * q + 0) * RDIM);
        const float4* g1 = reinterpret_cast<const float4*>(G + (4 * q + 1) * RDIM);
        const float4* g2 = reinterpret_cast<const float4*>(G + (4 * q + 2) * RDIM);
        const float4* g3 = reinterpret_cast<const float4*>(G + (4 * q + 3) * RDIM);
        #pragma unroll
        for (int r4 = 0; r4 < 4; r4++) {
            const float4 a = __ldg(g0 + r4);
            const float4 b = __ldg(g1 + r4);
            const float4 c = __ldg(g2 + r4);
            const float4 d = __ldg(g3 + r4);
            Ga[r4 * 4 + 0] = pack2(a.x, b.x);  Gb[r4 * 4 + 0] = pack2(c.x, d.x);
            Ga[r4 * 4 + 1] = pack2(a.y, b.y);  Gb[r4 * 4 + 1] = pack2(c.y, d.y);
            Ga[r4 * 4 + 2] = pack2(a.z, b.z);  Gb[r4 * 4 + 2] = pack2(c.z, d.z);
            Ga[r4 * 4 + 3] = pack2(a.w, b.w);  Gb[r4 * 4 + 3] = pack2(c.w, d.w);
        }
    }

    const int warp   = blockIdx.x * (blockDim.x >> 5) + (threadIdx.x >> 5);
    const int nwarps = gridDim.x * (blockDim.x >> 5);

    // NPAIRS even, base even -> base+half < NPAIRS whenever base < NPAIRS.
    for (int base = warp * 2; base < NPAIRS; base += nwarps * 2) {
        const int p = base + half;

        const int ii = __ldg(pidx + p);
        const int jj = __ldg(pidx + NPAIRS + p);

        const float4* fr = reinterpret_cast<const float4*>(fij + (size_t)p * RDIM);
        const float4 f0 = __ldg(fr + 0);
        const float4 f1 = __ldg(fr + 1);
        const float4 f2 = __ldg(fr + 2);
        const float4 f3 = __ldg(fr + 3);

        const float4 y = __ldg(reinterpret_cast<const float4*>(
            g_yj + (size_t)jj * FDIM + q * 4));

        // f' for this lane's 4 features: 4 independent fma2 chains
        u64 a0 = 0ull, a1 = 0ull, b0 = 0ull, b1 = 0ull;
        #define STEP(r, fv) do {                       \
            const u64 s = splat2(fv);                  \
            if ((r) & 1) { a1 = fma2(s, Ga[r], a1); b1 = fma2(s, Gb[r], b1); } \
            else         { a0 = fma2(s, Ga[r], a0); b0 = fma2(s, Gb[r], b0); } \
        } while (0)
        STEP(0,  f0.x); STEP(1,  f0.y); STEP(2,  f0.z); STEP(3,  f0.w);
        STEP(4,  f1.x); STEP(5,  f1.y); STEP(6,  f1.z); STEP(7,  f1.w);
        STEP(8,  f2.x); STEP(9,  f2.y); STEP(10, f2.z); STEP(11, f2.w);
        STEP(12, f3.x); STEP(13, f3.y); STEP(14, f3.z); STEP(15, f3.w);
        #undef STEP

        const float2 mA = unpack2(mul2(add2(a0, a1), pack2(y.x, y.y)));
        const float2 mB = unpack2(mul2(add2(b0, b1), pack2(y.z, y.w)));

        float* dst = g_acc + (size_t)ii * FDIM + q * 4;   // 16B aligned
        asm volatile("red.global.add.v4.f32 [%0], {%1,%2,%3,%4};"
                     :: "l"(dst), "f"(mA.x), "f"(mA.y), "f"(mB.x), "f"(mB.y)
                     : "memory");
    }
}

// ---------------------------------------------------------------------------
// Kernel 3: epilogue. 7 chained 64x64 matmuls per atom, 4-atom register
// blocking + f32x2. 512 threads = 32 atom-groups x 16 col-groups.
// ---------------------------------------------------------------------------
#define EPI_TILE 128
#define VPAD 68

__device__ __forceinline__ void gemm_tile(const float* __restrict__ W,
                                          const float* __restrict__ rows,
                                          int ag, int q,
                                          const float* __restrict__ bias,
                                          float4 o[4])
{
    const u64 b0 = pack2(bias[q * 4 + 0], bias[q * 4 + 1]);
    const u64 b1 = pack2(bias[q * 4 + 2], bias[q * 4 + 3]);
    u64 acc[4][2];
    #pragma unroll
    for (int i = 0; i < 4; i++) { acc[i][0] = b0; acc[i][1] = b1; }

    #pragma unroll 4
    for (int k0 = 0; k0 < FDIM; k0 += 4) {
        ulonglong2 w[4];
        #pragma unroll
        for (int j = 0; j < 4; j++)
            w[j] = *reinterpret_cast<const ulonglong2*>(W + (k0 + j) * 64 + q * 4);
        #pragma unroll
        for (int i = 0; i < 4; i++) {
            const float4 v = *reinterpret_cast<const float4*>(
                rows + (ag * 4 + i) * VPAD + k0);
            acc[i][0] = fma2(splat2(v.x), w[0].x, acc[i][0]);
            acc[i][1] = fma2(splat2(v.x), w[0].y, acc[i][1]);
            acc[i][0] = fma2(splat2(v.y), w[1].x, acc[i][0]);
            acc[i][1] = fma2(splat2(v.y), w[1].y, acc[i][1]);
            acc[i][0] = fma2(splat2(v.z), w[2].x, acc[i][0]);
            acc[i][1] = fma2(splat2(v.z), w[2].y, acc[i][1]);
            acc[i][0] = fma2(splat2(v.w), w[3].x, acc[i][0]);
            acc[i][1] = fma2(splat2(v.w), w[3].y, acc[i][1]);
        }
    }
    #pragma unroll
    for (int i = 0; i < 4; i++) {
        const float2 p0 = unpack2(acc[i][0]);
        const float2 p1 = unpack2(acc[i][1]);
        o[i] = make_float4(p0.x, p0.y, p1.x, p1.y);
    }
}

__global__ void __launch_bounds__(512) epi_kernel(
    const float* __restrict__ rW1, const float* __restrict__ rb1,
    const float* __restrict__ rW2, const float* __restrict__ rb2,
    const float* __restrict__ Wv,  const float* __restrict__ bv,
    float* __restrict__ out)
{
    extern __shared__ float sm[];
    float* Wsh = sm;
    float* vs  = Wsh + 7 * 4096;
    float* hs  = vs  + EPI_TILE * VPAD;
    float* b1s = hs  + EPI_TILE * VPAD;
    float* b2s = b1s + 192;
    float* bvs = b2s + 192;

    const int tid = threadIdx.x;
    for (int i = tid; i < 3 * 4096; i += 512) {
        Wsh[i] = rW1[i];
        Wsh[3 * 4096 + i] = rW2[i];
    }
    for (int i = tid; i < 4096; i += 512) Wsh[6 * 4096 + i] = Wv[i];
    if (tid < 192) { b1s[tid] = rb1[tid]; b2s[tid] = rb2[tid]; }
    if (tid < 64) bvs[tid] = bv[tid];
    __syncthreads();

    const int q  = tid & 15;
    const int ag = tid >> 4;

    const int ntiles = (NATOMS + EPI_TILE - 1) / EPI_TILE;
    for (int t = blockIdx.x; t < ntiles; t += gridDim.x) {
        const int abase = t * EPI_TILE + ag * 4;

        float4 v[4];
        #pragma unroll
        for (int i = 0; i < 4; i++) {
            const int atom = abase + i;
            v[i] = (atom < NATOMS)
                 ? *reinterpret_cast<const float4*>(g_acc + (size_t)atom * FDIM + q * 4)
                 : make_float4(0.f, 0.f, 0.f, 0.f);
            *reinterpret_cast<float4*>(vs + (ag * 4 + i) * VPAD + q * 4) = v[i];
        }
        __syncthreads();

        #pragma unroll 1
        for (int l = 0; l < 3; l++) {
            float4 h[4];
            gemm_tile(Wsh + l * 4096, vs, ag, q, b1s + l * 64, h);
            #pragma unroll
            for (int i = 0; i < 4; i++) {
                h[i].x = sp(h[i].x); h[i].y = sp(h[i].y);
                h[i].z = sp(h[i].z); h[i].w = sp(h[i].w);
                *reinterpret_cast<float4*>(hs + (ag * 4 + i) * VPAD + q * 4) = h[i];
            }
            __syncthreads();

            float4 d[4];
            gemm_tile(Wsh + (3 + l) * 4096, hs, ag, q, b2s + l * 64, d);
            #pragma unroll
            for (int i = 0; i < 4; i++) {
                v[i].x += d[i].x; v[i].y += d[i].y;
                v[i].z += d[i].z; v[i].w += d[i].w;
                *reinterpret_cast<float4*>(vs + (ag * 4 + i) * VPAD + q * 4) = v[i];
            }
            __syncthreads();
        }

        #pragma unroll
        for (int i = 0; i < 4; i++) {
            const float4 s = make_float4(sp(v[i].x), sp(v[i].y), sp(v[i].z), sp(v[i].w));
            *reinterpret_cast<float4*>(hs + (ag * 4 + i) * VPAD + q * 4) = s;
        }
        __syncthreads();

        float4 o[4];
        gemm_tile(Wsh + 6 * 4096, hs, ag, q, bvs, o);
        #pragma unroll
        for (int i = 0; i < 4; i++) {
            const int atom = abase + i;
            if (atom < NATOMS)
                *reinterpret_cast<float4*>(out + (size_t)atom * FDIM + q * 4) = o[i];
        }
        __syncthreads();
    }
}

// ---------------------------------------------------------------------------
extern "C" void kernel_launch(void* const* d_in, const int* in_sizes, int n_in,
                              void* d_out, int out_size)
{
    const int*   pidx = (const int*)  d_in[0];
    const float* fij  = (const float*)d_in[1];
    const float* emb  = (const float*)d_in[3];
    const float* G    = (const float*)d_in[4];
    const float* Wi   = (const float*)d_in[5];
    const float* bi   = (const float*)d_in[6];
    const float* Wj   = (const float*)d_in[7];
    const float* bj   = (const float*)d_in[8];
    const float* rW1  = (const float*)d_in[9];
    const float* rb1  = (const float*)d_in[10];
    const float* rW2  = (const float*)d_in[11];
    const float* rb2  = (const float*)d_in[12];
    const float* Wv   = (const float*)d_in[13];
    const float* bv   = (const float*)d_in[14];
    float* out = (float*)d_out;

    // Kernel 1: node transforms (g_acc = x_i', g_yj = x_j')
    node_kernel<<<296, 512>>>(emb, Wi, bi, Wj, bj);

    // Kernel 2: half-warp-per-pair messages, G in registers, red.v4 scatter
    pair_kernel<<<592, 256>>>(pidx, fij, G);

    // Kernel 3: residual MLP chain + output projection
    const int epi_smem = (7 * 4096 + 2 * EPI_TILE * VPAD + 192 + 192 + 64) * 4;
    cudaFuncSetAttribute(epi_kernel, cudaFuncAttributeMaxDynamicSharedMemorySize,
                         epi_smem);
    epi_kernel<<<148, 512, epi_smem>>>(rW1, rb1, rW2, rb2, Wv, bv, out);
}